// round 9
// baseline (speedup 1.0000x reference)
#include <cuda_runtime.h>
#include <cuda_bf16.h>
#include <math.h>
#include <stdint.h>

// ---------------------------------------------------------------------------
// Problem constants
// ---------------------------------------------------------------------------
#define Bn 2
#define Ln 1024
#define Dn 2048
#define Nn 16
#define Rn 128
#define En 160          // DT_RANK + 2*D_STATE
#define Mn (Bn*Ln)      // 2048 rows (b,l)
#define NCHUNK 32
#define LCH (Ln/NCHUNK) // 32 steps per chunk
#define SPLITK 8

// ---------------------------------------------------------------------------
// Device scratch (no allocations allowed)
// ---------------------------------------------------------------------------
__device__ __nv_bfloat16  g_uhi[(size_t)Mn*Dn];      // u split-bf16 hi
__device__ __nv_bfloat16  g_ulo[(size_t)Mn*Dn];      // u split-bf16 lo
__device__ __nv_bfloat16  g_w1hi[En*Dn];             // xproj_w hi
__device__ __nv_bfloat16  g_w1lo[En*Dn];
__device__ __nv_bfloat16  g_w2hi[Dn*Rn];             // dtproj_w hi
__device__ __nv_bfloat16  g_w2lo[Dn*Rn];
__device__ __nv_bfloat16  g_dthi[Mn*Rn];             // dt (x_dbl[:, :128]) hi
__device__ __nv_bfloat16  g_dtlo[Mn*Rn];
__device__ float          g_part[SPLITK*Mn*En];      // gemm1 split-K partials
__device__ float          g_xdbl[Mn*En];             // x_dbl = [dt | B | C]
__device__ float          g_delta[(size_t)Mn*Dn];    // softplus(...)
__device__ float          g_Aneg[Dn*Nn];             // A = -exp(A_log)
__device__ float          g_cA[Bn*NCHUNK*Nn*Dn];     // chunk prod(a)
__device__ float          g_cB[Bn*NCHUNK*Nn*Dn];     // chunk composed b
__device__ float          g_hin[Bn*NCHUNK*Nn*Dn];    // incoming h per chunk

// ---------------------------------------------------------------------------
// Warp-MMA + cp.async helpers
// ---------------------------------------------------------------------------
__device__ __forceinline__ uint32_t smem_u32(const void* p) {
    uint32_t a;
    asm("{ .reg .u64 t; cvta.to.shared.u64 t, %1; cvt.u32.u64 %0, t; }"
        : "=r"(a) : "l"(p));
    return a;
}
__device__ __forceinline__ void cp16(uint32_t dst, const void* src) {
    asm volatile("cp.async.cg.shared.global [%0], [%1], 16;"
                 :: "r"(dst), "l"(src));
}
#define CP_COMMIT() asm volatile("cp.async.commit_group;" ::: "memory")
#define CP_WAIT1()  asm volatile("cp.async.wait_group 1;" ::: "memory")

__device__ __forceinline__ void ldsm4(uint32_t* r, uint32_t addr) {
    asm volatile("ldmatrix.sync.aligned.m8n8.x4.shared.b16 {%0,%1,%2,%3}, [%4];"
                 : "=r"(r[0]), "=r"(r[1]), "=r"(r[2]), "=r"(r[3]) : "r"(addr));
}
__device__ __forceinline__ void ldsm2(uint32_t* r, uint32_t addr) {
    asm volatile("ldmatrix.sync.aligned.m8n8.x2.shared.b16 {%0,%1}, [%2];"
                 : "=r"(r[0]), "=r"(r[1]) : "r"(addr));
}
__device__ __forceinline__ void mma_bf16(float* c, const uint32_t* a, const uint32_t* b) {
    asm volatile(
        "mma.sync.aligned.m16n8k16.row.col.f32.bf16.bf16.f32 "
        "{%0,%1,%2,%3}, {%4,%5,%6,%7}, {%8,%9}, {%0,%1,%2,%3};"
        : "+f"(c[0]), "+f"(c[1]), "+f"(c[2]), "+f"(c[3])
        : "r"(a[0]), "r"(a[1]), "r"(a[2]), "r"(a[3]), "r"(b[0]), "r"(b[1]));
}

// ---------------------------------------------------------------------------
// 1) Depthwise causal conv1d (k=4) + bias; float4-vectorized, emit split-bf16
// ---------------------------------------------------------------------------
__global__ void conv_kernel(const float* __restrict__ x,
                            const float* __restrict__ cw,
                            const float* __restrict__ cb) {
    int i4 = blockIdx.x * 256 + threadIdx.x;    // < Mn*Dn/4
    int idx = i4 * 4;                           // = (b*L + l)*D + d, d%4==0
    int d = idx & (Dn - 1);
    int l = (idx >> 11) & (Ln - 1);
    float4 w0 = *(const float4*)(cw + (d + 0) * 4);
    float4 w1 = *(const float4*)(cw + (d + 1) * 4);
    float4 w2 = *(const float4*)(cw + (d + 2) * 4);
    float4 w3 = *(const float4*)(cw + (d + 3) * 4);
    float4 acc = *(const float4*)(cb + d);
    const float* wj0 = (const float*)&w0;
    const float* wj1 = (const float*)&w1;
    const float* wj2 = (const float*)&w2;
    const float* wj3 = (const float*)&w3;
#pragma unroll
    for (int j = 0; j < 4; j++) {
        if (l - 3 + j >= 0) {
            float4 xv = *(const float4*)(x + idx + (j - 3) * Dn);
            acc.x += xv.x * wj0[j];
            acc.y += xv.y * wj1[j];
            acc.z += xv.z * wj2[j];
            acc.w += xv.w * wj3[j];
        }
    }
    float vv[4] = {acc.x, acc.y, acc.z, acc.w};
    __nv_bfloat16 hi4[4], lo4[4];
#pragma unroll
    for (int t = 0; t < 4; t++) {
        hi4[t] = __float2bfloat16(vv[t]);
        lo4[t] = __float2bfloat16(vv[t] - __bfloat162float(hi4[t]));
    }
    *(uint2*)(g_uhi + idx) = *(uint2*)hi4;
    *(uint2*)(g_ulo + idx) = *(uint2*)lo4;
}

// ---------------------------------------------------------------------------
// 2) A = -exp(A_log)
// ---------------------------------------------------------------------------
__global__ void aprep_kernel(const float* __restrict__ alog) {
    int i = blockIdx.x * 256 + threadIdx.x;
    if (i < Dn * Nn) g_Aneg[i] = -expf(alog[i]);
}

// ---------------------------------------------------------------------------
// 2b) Weight split-bf16 conversion (W1: 160x2048, W2: 2048x128)
// ---------------------------------------------------------------------------
__global__ void wconv_kernel(const float* __restrict__ W1,
                             const float* __restrict__ W2) {
    int i = blockIdx.x * 256 + threadIdx.x;
    if (i < En * Dn) {
        float v = W1[i];
        __nv_bfloat16 h = __float2bfloat16(v);
        g_w1hi[i] = h;
        g_w1lo[i] = __float2bfloat16(v - __bfloat162float(h));
    }
    if (i < Dn * Rn) {
        float v = W2[i];
        __nv_bfloat16 h = __float2bfloat16(v);
        g_w2hi[i] = h;
        g_w2lo[i] = __float2bfloat16(v - __bfloat162float(h));
    }
}

// ---------------------------------------------------------------------------
// 3) GEMM1 (mma.sync, split-bf16, 3-stage cp.async):
//    part[s][m][e] = sum_{k in split} u[m][k] * W1[e][k]
//    Block 64x160, 8 warps (2m x 4n), BK=32, 8 k-blocks. grid (32, 8).
// ---------------------------------------------------------------------------
#define PAD 40            // smem row stride in bf16 (80 B): conflict-free
#define G1_AHI 0
#define G1_ALO 5120
#define G1_BHI 10240
#define G1_BLO 23040
#define G1_STAGE 35840
#define G1_SMEM (3 * G1_STAGE)

__global__ void __launch_bounds__(256, 2) gemm1_mma() {
    extern __shared__ char smem[];
    uint32_t sb = smem_u32(smem);
    int tid = threadIdx.x;
    int lane = tid & 31, wid = tid >> 5;
    int wm = wid & 1, wn = wid >> 1;       // 2 x 4 warps
    int m0 = blockIdx.x * 64;
    int kbase = blockIdx.y * (Dn / SPLITK);

    float acc[2][5][4];
#pragma unroll
    for (int i = 0; i < 2; i++)
#pragma unroll
        for (int j = 0; j < 5; j++)
#pragma unroll
            for (int t = 0; t < 4; t++) acc[i][j][t] = 0.f;

    int a_r = (lane & 7) + ((lane >> 3) & 1) * 8;
    int a_c = (lane >> 4) * 8;
    int b_r4 = (lane & 7) + (lane >> 4) * 8;
    int b_c  = ((lane >> 3) & 1) * 8;
    int b_r2 = lane & 7;

    auto load_stage = [&](int st, int kcol) {
        uint32_t sbase = sb + st * G1_STAGE;
        {                                             // A: 256 chunks
            int row = tid >> 2, c16 = tid & 3;
            uint32_t so = sbase + row * 80 + c16 * 16;
            size_t g = (size_t)(m0 + row) * Dn + kcol + c16 * 8;
            cp16(so + G1_AHI, g_uhi + g);
            cp16(so + G1_ALO, g_ulo + g);
        }
#pragma unroll
        for (int i = 0; i < 3; i++) {                 // B: 640 chunks
            int cidx = tid + i * 256;
            if (cidx < 640) {
                int row = cidx >> 2, c16 = cidx & 3;
                uint32_t so = sbase + row * 80 + c16 * 16;
                size_t g = (size_t)row * Dn + kcol + c16 * 8;
                cp16(so + G1_BHI, g_w1hi + g);
                cp16(so + G1_BLO, g_w1lo + g);
            }
        }
        CP_COMMIT();
    };

    load_stage(0, kbase);
    load_stage(1, kbase + 32);
    for (int kb = 0; kb < 8; kb++) {
        CP_WAIT1();                  // oldest outstanding stage (kb) done
        __syncthreads();
        if (kb + 2 < 8) load_stage((kb + 2) % 3, kbase + (kb + 2) * 32);

        uint32_t sbase = sb + (kb % 3) * G1_STAGE;
#pragma unroll
        for (int kk = 0; kk < 32; kk += 16) {
            uint32_t ah[2][4], al[2][4], bh[5][2], bl[5][2];
#pragma unroll
            for (int mt = 0; mt < 2; mt++) {
                uint32_t a = sbase + G1_AHI +
                    (uint32_t)(((wm * 32 + mt * 16 + a_r) * PAD + kk + a_c) * 2);
                ldsm4(ah[mt], a);
                ldsm4(al[mt], a + (G1_ALO - G1_AHI));
            }
#pragma unroll
            for (int g = 0; g < 2; g++) {
                uint32_t a = sbase + G1_BHI +
                    (uint32_t)(((wn * 40 + g * 16 + b_r4) * PAD + kk + b_c) * 2);
                uint32_t t[4];
                ldsm4(t, a);
                bh[2 * g][0] = t[0]; bh[2 * g][1] = t[1];
                bh[2 * g + 1][0] = t[2]; bh[2 * g + 1][1] = t[3];
                ldsm4(t, a + (G1_BLO - G1_BHI));
                bl[2 * g][0] = t[0]; bl[2 * g][1] = t[1];
                bl[2 * g + 1][0] = t[2]; bl[2 * g + 1][1] = t[3];
            }
            {
                uint32_t a = sbase + G1_BHI +
                    (uint32_t)(((wn * 40 + 32 + b_r2) * PAD + kk + b_c) * 2);
                ldsm2(bh[4], a);
                ldsm2(bl[4], a + (G1_BLO - G1_BHI));
            }
#pragma unroll
            for (int mt = 0; mt < 2; mt++)
#pragma unroll
                for (int nt = 0; nt < 5; nt++) {
                    mma_bf16(acc[mt][nt], ah[mt], bh[nt]);
                    mma_bf16(acc[mt][nt], ah[mt], bl[nt]);
                    mma_bf16(acc[mt][nt], al[mt], bh[nt]);
                }
        }
    }

    // Epilogue -> split-K partials
    float* outp = g_part + (size_t)blockIdx.y * (Mn * En);
#pragma unroll
    for (int mt = 0; mt < 2; mt++) {
        int row = m0 + wm * 32 + mt * 16 + (lane >> 2);
#pragma unroll
        for (int nt = 0; nt < 5; nt++) {
            int col = wn * 40 + nt * 8 + (lane & 3) * 2;
            *(float2*)(outp + (size_t)row * En + col) =
                make_float2(acc[mt][nt][0], acc[mt][nt][1]);
            *(float2*)(outp + (size_t)(row + 8) * En + col) =
                make_float2(acc[mt][nt][2], acc[mt][nt][3]);
        }
    }
}

// ---------------------------------------------------------------------------
// 4) Reduce split-K partials -> x_dbl (float4); emit dt split-bf16 for e<128
// ---------------------------------------------------------------------------
__global__ void reduce1_kernel() {
    int i4 = blockIdx.x * 256 + threadIdx.x;  // < Mn*En/4
    int i = i4 * 4;
    float4 s = make_float4(0.f, 0.f, 0.f, 0.f);
#pragma unroll
    for (int p = 0; p < SPLITK; p++) {
        float4 v = *(const float4*)(g_part + (size_t)p * (Mn * En) + i);
        s.x += v.x; s.y += v.y; s.z += v.z; s.w += v.w;
    }
    *(float4*)(g_xdbl + i) = s;
    int m = i / En;
    int e = i - m * En;
    if (e < Rn) {
        float vv[4] = {s.x, s.y, s.z, s.w};
        __nv_bfloat16 hi4[4], lo4[4];
#pragma unroll
        for (int t = 0; t < 4; t++) {
            hi4[t] = __float2bfloat16(vv[t]);
            lo4[t] = __float2bfloat16(vv[t] - __bfloat162float(hi4[t]));
        }
        *(uint2*)(g_dthi + m * Rn + e) = *(uint2*)hi4;
        *(uint2*)(g_dtlo + m * Rn + e) = *(uint2*)lo4;
    }
}

// ---------------------------------------------------------------------------
// 5) GEMM2 (mma.sync, split-bf16, 3-stage cp.async) + bias + softplus:
//    delta[m][d] = softplus(sum_r dt[m][r]*W2[d][r] + b2[d])
//    Block 64x128, 8 warps (2m x 4n), BK=32, 4 k-blocks. grid (32, 16).
// ---------------------------------------------------------------------------
#define G2_AHI 0
#define G2_ALO 5120
#define G2_BHI 10240
#define G2_BLO 20480
#define G2_STAGE 30720
#define G2_SMEM (3 * G2_STAGE)

__global__ void __launch_bounds__(256, 2) gemm2_mma(const float* __restrict__ b2) {
    extern __shared__ char smem[];
    uint32_t sb = smem_u32(smem);
    int tid = threadIdx.x;
    int lane = tid & 31, wid = tid >> 5;
    int wm = wid & 1, wn = wid >> 1;       // 2 x 4 warps
    int m0 = blockIdx.x * 64, n0 = blockIdx.y * 128;

    float acc[2][4][4];
#pragma unroll
    for (int i = 0; i < 2; i++)
#pragma unroll
        for (int j = 0; j < 4; j++)
#pragma unroll
            for (int t = 0; t < 4; t++) acc[i][j][t] = 0.f;

    int a_r = (lane & 7) + ((lane >> 3) & 1) * 8;
    int a_c = (lane >> 4) * 8;
    int b_r4 = (lane & 7) + (lane >> 4) * 8;
    int b_c  = ((lane >> 3) & 1) * 8;

    auto load_stage = [&](int st, int kcol) {
        uint32_t sbase = sb + st * G2_STAGE;
        {                                             // A: 256 chunks
            int row = tid >> 2, c16 = tid & 3;
            uint32_t so = sbase + row * 80 + c16 * 16;
            size_t g = (size_t)(m0 + row) * Rn + kcol + c16 * 8;
            cp16(so + G2_AHI, g_dthi + g);
            cp16(so + G2_ALO, g_dtlo + g);
        }
#pragma unroll
        for (int i = 0; i < 2; i++) {                 // B: 512 chunks
            int cidx = tid + i * 256;
            int row = cidx >> 2, c16 = cidx & 3;
            uint32_t so = sbase + row * 80 + c16 * 16;
            size_t g = (size_t)(n0 + row) * Rn + kcol + c16 * 8;
            cp16(so + G2_BHI, g_w2hi + g);
            cp16(so + G2_BLO, g_w2lo + g);
        }
        CP_COMMIT();
    };

    load_stage(0, 0);
    load_stage(1, 32);
    for (int kb = 0; kb < 4; kb++) {
        CP_WAIT1();
        __syncthreads();
        if (kb + 2 < 4) load_stage((kb + 2) % 3, (kb + 2) * 32);

        uint32_t sbase = sb + (kb % 3) * G2_STAGE;
#pragma unroll
        for (int kk = 0; kk < 32; kk += 16) {
            uint32_t ah[2][4], al[2][4], bh[4][2], bl[4][2];
#pragma unroll
            for (int mt = 0; mt < 2; mt++) {
                uint32_t a = sbase + G2_AHI +
                    (uint32_t)(((wm * 32 + mt * 16 + a_r) * PAD + kk + a_c) * 2);
                ldsm4(ah[mt], a);
                ldsm4(al[mt], a + (G2_ALO - G2_AHI));
            }
#pragma unroll
            for (int g = 0; g < 2; g++) {
                uint32_t a = sbase + G2_BHI +
                    (uint32_t)(((wn * 32 + g * 16 + b_r4) * PAD + kk + b_c) * 2);
                uint32_t t[4];
                ldsm4(t, a);
                bh[2 * g][0] = t[0]; bh[2 * g][1] = t[1];
                bh[2 * g + 1][0] = t[2]; bh[2 * g + 1][1] = t[3];
                ldsm4(t, a + (G2_BLO - G2_BHI));
                bl[2 * g][0] = t[0]; bl[2 * g][1] = t[1];
                bl[2 * g + 1][0] = t[2]; bl[2 * g + 1][1] = t[3];
            }
#pragma unroll
            for (int mt = 0; mt < 2; mt++)
#pragma unroll
                for (int nt = 0; nt < 4; nt++) {
                    mma_bf16(acc[mt][nt], ah[mt], bh[nt]);
                    mma_bf16(acc[mt][nt], ah[mt], bl[nt]);
                    mma_bf16(acc[mt][nt], al[mt], bh[nt]);
                }
        }
    }

    // Epilogue: bias + softplus straight from registers
#pragma unroll
    for (int mt = 0; mt < 2; mt++) {
        int row = m0 + wm * 32 + mt * 16 + (lane >> 2);
#pragma unroll
        for (int nt = 0; nt < 4; nt++) {
            int col = n0 + wn * 32 + nt * 8 + (lane & 3) * 2;
            float bb0 = __ldg(b2 + col), bb1 = __ldg(b2 + col + 1);
            float t0 = acc[mt][nt][0] + bb0, t1 = acc[mt][nt][1] + bb1;
            float t2 = acc[mt][nt][2] + bb0, t3 = acc[mt][nt][3] + bb1;
            t0 = (t0 > 20.f) ? t0 : log1pf(__expf(t0));
            t1 = (t1 > 20.f) ? t1 : log1pf(__expf(t1));
            t2 = (t2 > 20.f) ? t2 : log1pf(__expf(t2));
            t3 = (t3 > 20.f) ? t3 : log1pf(__expf(t3));
            *(float2*)(g_delta + (size_t)row * Dn + col) = make_float2(t0, t1);
            *(float2*)(g_delta + (size_t)(row + 8) * Dn + col) = make_float2(t2, t3);
        }
    }
}

// ---------------------------------------------------------------------------
// 6) Scan pass 1: per (b,d,chunk) compute (prod a, composed b) over LCH steps
// ---------------------------------------------------------------------------
__global__ void __launch_bounds__(256) scan1_kernel() {
    __shared__ float Bsm[LCH][Nn];
    int tid = threadIdx.x;
    int d = blockIdx.x * 256 + tid;
    int c = blockIdx.y;
    int b = blockIdx.z;
    int lbase = b * Ln + c * LCH;
#pragma unroll
    for (int i = 0; i < (LCH * Nn) / 256; i++) {
        int f = tid + i * 256; int l = f >> 4, n = f & 15;
        Bsm[l][n] = g_xdbl[(lbase + l) * En + Rn + n];
    }
    __syncthreads();

    float A2[Nn];
#pragma unroll
    for (int n = 0; n < Nn; n++) A2[n] = g_Aneg[d * Nn + n];
    bool unif = true;
#pragma unroll
    for (int n = 1; n < Nn; n++) unif = unif && (A2[n] == A2[0]);

    float Ap[Nn], Bs[Nn];
#pragma unroll
    for (int n = 0; n < Nn; n++) { Ap[n] = 1.f; Bs[n] = 0.f; }

    const float* dptr = g_delta + (size_t)lbase * Dn + d;
    const __nv_bfloat16* uh = g_uhi + (size_t)lbase * Dn + d;
    const __nv_bfloat16* ul = g_ulo + (size_t)lbase * Dn + d;

    if (unif) {
        float a0 = A2[0];
        float ap = 1.f;
#pragma unroll 4
        for (int l = 0; l < LCH; l++) {
            float dl = dptr[(size_t)l * Dn];
            float uu = __bfloat162float(uh[(size_t)l * Dn]) +
                       __bfloat162float(ul[(size_t)l * Dn]);
            float s = dl * uu;
            float dA = __expf(dl * a0);
            ap *= dA;
#pragma unroll
            for (int n = 0; n < Nn; n++) Bs[n] = dA * Bs[n] + s * Bsm[l][n];
        }
#pragma unroll
        for (int n = 0; n < Nn; n++) Ap[n] = ap;
    } else {
        for (int l = 0; l < LCH; l++) {
            float dl = dptr[(size_t)l * Dn];
            float uu = __bfloat162float(uh[(size_t)l * Dn]) +
                       __bfloat162float(ul[(size_t)l * Dn]);
            float s = dl * uu;
#pragma unroll
            for (int n = 0; n < Nn; n++) {
                float dA = __expf(dl * A2[n]);
                Ap[n] *= dA;
                Bs[n] = dA * Bs[n] + s * Bsm[l][n];
            }
        }
    }
    size_t base = ((size_t)(b * NCHUNK + c) * Nn) * Dn + d;
#pragma unroll
    for (int n = 0; n < Nn; n++) {
        g_cA[base + (size_t)n * Dn] = Ap[n];
        g_cB[base + (size_t)n * Dn] = Bs[n];
    }
}

// ---------------------------------------------------------------------------
// 7) Inter-chunk scan: per (b,d,n) propagate h across NCHUNK chunks
// ---------------------------------------------------------------------------
__global__ void scanmid_kernel() {
    int idx = blockIdx.x * 256 + threadIdx.x;  // b*(N*D) + n*D + d
    int d = idx & (Dn - 1);
    int n = (idx >> 11) & (Nn - 1);
    int b = idx >> 15;
    float h = 0.f;
    for (int c = 0; c < NCHUNK; c++) {
        size_t off = ((size_t)(b * NCHUNK + c) * Nn + n) * Dn + d;
        g_hin[off] = h;
        h = g_cA[off] * h + g_cB[off];
    }
}

// ---------------------------------------------------------------------------
// 8) Scan pass 2: replay with correct h_in, emit y
// ---------------------------------------------------------------------------
__global__ void __launch_bounds__(256) scan2_kernel(float* __restrict__ y,
                                                    const float* __restrict__ Dskip) {
    __shared__ float Bsm[LCH][Nn];
    __shared__ float Csm[LCH][Nn];
    int tid = threadIdx.x;
    int d = blockIdx.x * 256 + tid;
    int c = blockIdx.y;
    int b = blockIdx.z;
    int lbase = b * Ln + c * LCH;
#pragma unroll
    for (int i = 0; i < (LCH * Nn) / 256; i++) {
        int f = tid + i * 256; int l = f >> 4, n = f & 15;
        Bsm[l][n] = g_xdbl[(lbase + l) * En + Rn + n];
        Csm[l][n] = g_xdbl[(lbase + l) * En + Rn + Nn + n];
    }
    __syncthreads();

    float A2[Nn];
#pragma unroll
    for (int n = 0; n < Nn; n++) A2[n] = g_Aneg[d * Nn + n];
    bool unif = true;
#pragma unroll
    for (int n = 1; n < Nn; n++) unif = unif && (A2[n] == A2[0]);

    float h[Nn];
    size_t base = ((size_t)(b * NCHUNK + c) * Nn) * Dn + d;
#pragma unroll
    for (int n = 0; n < Nn; n++) h[n] = g_hin[base + (size_t)n * Dn];

    float dsk = Dskip[d];
    const float* dptr = g_delta + (size_t)lbase * Dn + d;
    const __nv_bfloat16* uh = g_uhi + (size_t)lbase * Dn + d;
    const __nv_bfloat16* ul = g_ulo + (size_t)lbase * Dn + d;
    float* yptr = y + (size_t)lbase * Dn + d;

    if (unif) {
        float a0 = A2[0];
#pragma unroll 4
        for (int l = 0; l < LCH; l++) {
            float dl = dptr[(size_t)l * Dn];
            float uu = __bfloat162float(uh[(size_t)l * Dn]) +
                       __bfloat162float(ul[(size_t)l * Dn]);
            float s = dl * uu;
            float dA = __expf(dl * a0);
            float acc = 0.f;
#pragma unroll
            for (int n = 0; n < Nn; n++) {
                h[n] = dA * h[n] + s * Bsm[l][n];
                acc += h[n] * Csm[l][n];
            }
            yptr[(size_t)l * Dn] = acc + uu * dsk;
        }
    } else {
        for (int l = 0; l < LCH; l++) {
            float dl = dptr[(size_t)l * Dn];
            float uu = __bfloat162float(uh[(size_t)l * Dn]) +
                       __bfloat162float(ul[(size_t)l * Dn]);
            float s = dl * uu;
            float acc = 0.f;
#pragma unroll
            for (int n = 0; n < Nn; n++) {
                float dA = __expf(dl * A2[n]);
                h[n] = dA * h[n] + s * Bsm[l][n];
                acc += h[n] * Csm[l][n];
            }
            yptr[(size_t)l * Dn] = acc + uu * dsk;
        }
    }
}

// ---------------------------------------------------------------------------
// Launch
// ---------------------------------------------------------------------------
extern "C" void kernel_launch(void* const* d_in, const int* in_sizes, int n_in,
                              void* d_out, int out_size) {
    const float* x     = (const float*)d_in[0];
    const float* cw    = (const float*)d_in[1];
    const float* cb    = (const float*)d_in[2];
    const float* W1    = (const float*)d_in[3];
    const float* W2    = (const float*)d_in[4];
    const float* b2    = (const float*)d_in[5];
    const float* alog  = (const float*)d_in[6];
    const float* dskip = (const float*)d_in[7];
    float* y = (float*)d_out;

    cudaFuncSetAttribute(gemm1_mma, cudaFuncAttributeMaxDynamicSharedMemorySize, G1_SMEM);
    cudaFuncSetAttribute(gemm2_mma, cudaFuncAttributeMaxDynamicSharedMemorySize, G2_SMEM);

    conv_kernel<<<(Mn * Dn / 4) / 256, 256>>>(x, cw, cb);
    aprep_kernel<<<(Dn * Nn) / 256, 256>>>(alog);
    wconv_kernel<<<(En * Dn) / 256, 256>>>(W1, W2);
    gemm1_mma<<<dim3(Mn / 64, SPLITK), 256, G1_SMEM>>>();
    reduce1_kernel<<<(Mn * En / 4) / 256, 256>>>();
    gemm2_mma<<<dim3(Mn / 64, Dn / 128), 256, G2_SMEM>>>(b2);
    scan1_kernel<<<dim3(Dn / 256, NCHUNK, Bn), 256>>>();
    scanmid_kernel<<<(Bn * Nn * Dn) / 256, 256>>>();
    scan2_kernel<<<dim3(Dn / 256, NCHUNK, Bn), 256>>>(y, dskip);
}